// round 5
// baseline (speedup 1.0000x reference)
#include <cuda_runtime.h>
#include <math.h>

#define NN   50000
#define NE   500000
#define NG   50
#define NPG  1000
#define IND  128
#define H4   4
#define D1   64
#define D2   128
#define NB_SCAN ((NN + 1023) / 1024)   // 49

// ---------------- device scratch (no runtime allocation allowed) ----------------
__device__ float g_fs1[NN * H4 * D1];
__device__ float g_fd1[NN * H4 * D1];
__device__ float g_h1 [NN * D1];
__device__ float g_fs2[NN * H4 * D2];
__device__ float g_fd2[NN * H4 * D2];
__device__ float g_h2 [NN * D2];
__device__ int   g_cnt [NN];
__device__ int   g_ptr [NN + 1];
__device__ int   g_cur [NN];
__device__ int   g_csrc[NE];
__device__ int   g_bsum[64];

// ---------------- CSR build ----------------
__global__ void zero_cnt_kernel() {
    int i = blockIdx.x * blockDim.x + threadIdx.x;
    if (i < NN) g_cnt[i] = 0;
}

__global__ void hist_kernel(const int* __restrict__ dst) {
    int e = blockIdx.x * blockDim.x + threadIdx.x;
    if (e < NE) atomicAdd(&g_cnt[dst[e]], 1);
}

__global__ void scan1_kernel() {
    __shared__ int sh[1024];
    int i = blockIdx.x * 1024 + threadIdx.x;
    int v = (i < NN) ? g_cnt[i] : 0;
    sh[threadIdx.x] = v;
    __syncthreads();
    #pragma unroll
    for (int off = 1; off < 1024; off <<= 1) {
        int t = (threadIdx.x >= off) ? sh[threadIdx.x - off] : 0;
        __syncthreads();
        sh[threadIdx.x] += t;
        __syncthreads();
    }
    int incl = sh[threadIdx.x];
    if (i < NN) g_ptr[i] = incl - v;         // block-local exclusive
    if (threadIdx.x == 1023) g_bsum[blockIdx.x] = incl;
}

__global__ void scan2_kernel() {
    __shared__ int sh[64];
    int tid = threadIdx.x;
    int v = (tid < NB_SCAN) ? g_bsum[tid] : 0;
    sh[tid] = v;
    __syncthreads();
    #pragma unroll
    for (int off = 1; off < 64; off <<= 1) {
        int t = (tid >= off) ? sh[tid - off] : 0;
        __syncthreads();
        sh[tid] += t;
        __syncthreads();
    }
    if (tid < NB_SCAN) g_bsum[tid] = sh[tid] - v;  // exclusive across blocks
}

__global__ void scan3_kernel() {
    int i = blockIdx.x * 1024 + threadIdx.x;
    if (i < NN) {
        int p = g_ptr[i] + g_bsum[blockIdx.x];
        g_ptr[i] = p;
        g_cur[i] = p;
    }
    if (i == 0) g_ptr[NN] = NE;
}

__global__ void scatter_kernel(const int* __restrict__ src, const int* __restrict__ dst) {
    int e = blockIdx.x * blockDim.x + threadIdx.x;
    if (e < NE) {
        int d = dst[e];
        int pos = atomicAdd(&g_cur[d], 1);
        g_csrc[pos] = src[e];
    }
}

// ---------------- GEMM: C[n,m] = A[n,:]@W[:,m] + bias[m] ----------------
// A: [Nr, K] row-major, W: [K, M] row-major. BM=BN=64, BK=8, 256 thr, 4x4/thr.
__global__ void gemm_bias_kernel(const float* __restrict__ A, const float* __restrict__ W,
                                 const float* __restrict__ bias, float* __restrict__ C,
                                 int Nr, int K, int M) {
    __shared__ float As[8][64];
    __shared__ float Bs[8][64];
    int brow = blockIdx.y * 64;
    int bcol = blockIdx.x * 64;
    int tid = threadIdx.x;
    int tr = (tid / 16) * 4;
    int tc = (tid % 16) * 4;
    float acc[4][4] = {};

    for (int k0 = 0; k0 < K; k0 += 8) {
        #pragma unroll
        for (int e = tid; e < 512; e += 256) {
            int r = e / 8, c = e % 8;
            As[c][r] = (brow + r < Nr) ? A[(size_t)(brow + r) * K + k0 + c] : 0.0f;
        }
        #pragma unroll
        for (int e = tid; e < 512; e += 256) {
            int r = e / 64, c = e % 64;
            Bs[r][c] = W[(size_t)(k0 + r) * M + bcol + c];
        }
        __syncthreads();
        #pragma unroll
        for (int k = 0; k < 8; k++) {
            float a[4], b[4];
            #pragma unroll
            for (int i = 0; i < 4; i++) a[i] = As[k][tr + i];
            #pragma unroll
            for (int j = 0; j < 4; j++) b[j] = Bs[k][tc + j];
            #pragma unroll
            for (int i = 0; i < 4; i++)
                #pragma unroll
                for (int j = 0; j < 4; j++)
                    acc[i][j] += a[i] * b[j];
        }
        __syncthreads();
    }
    #pragma unroll
    for (int i = 0; i < 4; i++) {
        int r = brow + tr + i;
        if (r < Nr) {
            #pragma unroll
            for (int j = 0; j < 4; j++) {
                int c = bcol + tc + j;
                C[(size_t)r * M + c] = acc[i][j] + bias[c];
            }
        }
    }
}

// ---------------- GAT layer: warp per destination node, online softmax ----------------
// out[n,d] = max_h ( sum_e alpha[e,h] * fs[src_e, h, d] ), alpha = edge softmax over dst
template <int D>
__global__ void gat_node_kernel(const float* __restrict__ fs, const float* __restrict__ fd,
                                const float* __restrict__ attn,   // [4, D]
                                float* __restrict__ out) {        // [NN, D]
    constexpr int WI = D / 32;
    int warp = (blockIdx.x * blockDim.x + threadIdx.x) >> 5;
    if (warp >= NN) return;
    int lane = threadIdx.x & 31;
    int node = warp;
    int beg = g_ptr[node];
    int end = g_ptr[node + 1];

    float fdv[H4][WI], av[H4][WI];
    const float* fdrow = fd + (size_t)node * H4 * D;
    #pragma unroll
    for (int h = 0; h < H4; h++)
        #pragma unroll
        for (int i = 0; i < WI; i++) {
            fdv[h][i] = fdrow[h * D + lane + 32 * i];
            av[h][i]  = attn[h * D + lane + 32 * i];
        }

    float m[H4], s[H4], acc[H4][WI];
    #pragma unroll
    for (int h = 0; h < H4; h++) {
        m[h] = -3.0e38f; s[h] = 0.0f;
        #pragma unroll
        for (int i = 0; i < WI; i++) acc[h][i] = 0.0f;
    }

    for (int e = beg; e < end; e++) {
        int srcn = g_csrc[e];
        const float* fr = fs + (size_t)srcn * H4 * D;
        float frv[H4][WI];
        #pragma unroll
        for (int h = 0; h < H4; h++) {
            #pragma unroll
            for (int i = 0; i < WI; i++) frv[h][i] = fr[h * D + lane + 32 * i];
        }
        #pragma unroll
        for (int h = 0; h < H4; h++) {
            float p = 0.0f;
            #pragma unroll
            for (int i = 0; i < WI; i++) {
                float v = frv[h][i] + fdv[h][i];
                v = (v > 0.0f) ? v : 0.2f * v;   // leaky_relu slope 0.2
                p += av[h][i] * v;
            }
            #pragma unroll
            for (int off = 16; off > 0; off >>= 1)
                p += __shfl_xor_sync(0xffffffffu, p, off);
            // online softmax update (all lanes identical p)
            float nm = fmaxf(m[h], p);
            float cs = __expf(m[h] - p > 0.0f ? 0.0f : m[h] - nm);  // exp(m-nm), handles -inf
            cs = __expf(m[h] - nm);
            float w = __expf(p - nm);
            s[h] = s[h] * cs + w;
            #pragma unroll
            for (int i = 0; i < WI; i++)
                acc[h][i] = acc[h][i] * cs + w * frv[h][i];
            m[h] = nm;
        }
    }

    float* orow = out + (size_t)node * D;
    if (end > beg) {
        #pragma unroll
        for (int i = 0; i < WI; i++) {
            float o = -3.0e38f;
            #pragma unroll
            for (int h = 0; h < H4; h++) o = fmaxf(o, acc[h][i] / s[h]);
            orow[lane + 32 * i] = o;
        }
    } else {
        #pragma unroll
        for (int i = 0; i < WI; i++) orow[lane + 32 * i] = 0.0f;
    }
}

// ---------------- Global attention pooling: one block per graph ----------------
__global__ void pool_kernel(const float* __restrict__ h, const float* __restrict__ gw,
                            const float* __restrict__ gb, float* __restrict__ out) {
    __shared__ float gates[NPG];
    __shared__ float red[128];
    int g = blockIdx.x;
    int tid = threadIdx.x;
    int base = g * NPG;

    for (int n = tid; n < NPG; n += 128) {
        const float* row = h + (size_t)(base + n) * D2;
        float sdot = 0.0f;
        #pragma unroll 4
        for (int d = 0; d < D2; d++) sdot += row[d] * gw[d];
        gates[n] = sdot + gb[0];
    }
    __syncthreads();

    float mx = -3.0e38f;
    for (int n = tid; n < NPG; n += 128) mx = fmaxf(mx, gates[n]);
    red[tid] = mx;
    __syncthreads();
    for (int o = 64; o > 0; o >>= 1) {
        if (tid < o) red[tid] = fmaxf(red[tid], red[tid + o]);
        __syncthreads();
    }
    mx = red[0];
    __syncthreads();

    float ssum = 0.0f;
    for (int n = tid; n < NPG; n += 128) ssum += __expf(gates[n] - mx);
    red[tid] = ssum;
    __syncthreads();
    for (int o = 64; o > 0; o >>= 1) {
        if (tid < o) red[tid] += red[tid + o];
        __syncthreads();
    }
    float S = red[0];

    float acc = 0.0f;
    for (int n = 0; n < NPG; n++) {
        float w = __expf(gates[n] - mx);
        acc += w * h[(size_t)(base + n) * D2 + tid];
    }
    out[g * D2 + tid] = acc / S;
}

// ---------------- launch ----------------
extern "C" void kernel_launch(void* const* d_in, const int* in_sizes, int n_in,
                              void* d_out, int out_size) {
    const float* x        = (const float*)d_in[0];
    const int*   edge_src = (const int*)  d_in[1];
    const int*   edge_dst = (const int*)  d_in[2];
    // d_in[3] = node_graph (graphs are contiguous blocks of 1000 nodes)
    const float* Wl1   = (const float*)d_in[4];
    const float* bl1   = (const float*)d_in[5];
    const float* Wr1   = (const float*)d_in[6];
    const float* br1   = (const float*)d_in[7];
    const float* attn1 = (const float*)d_in[8];
    const float* Wl2   = (const float*)d_in[9];
    const float* bl2   = (const float*)d_in[10];
    const float* Wr2   = (const float*)d_in[11];
    const float* br2   = (const float*)d_in[12];
    const float* attn2 = (const float*)d_in[13];
    const float* gate_w = (const float*)d_in[14];
    const float* gate_b = (const float*)d_in[15];
    float* out = (float*)d_out;

    float *fs1, *fd1, *h1, *fs2, *fd2, *h2;
    cudaGetSymbolAddress((void**)&fs1, g_fs1);
    cudaGetSymbolAddress((void**)&fd1, g_fd1);
    cudaGetSymbolAddress((void**)&h1,  g_h1);
    cudaGetSymbolAddress((void**)&fs2, g_fs2);
    cudaGetSymbolAddress((void**)&fd2, g_fd2);
    cudaGetSymbolAddress((void**)&h2,  g_h2);

    // CSR by destination
    zero_cnt_kernel<<<(NN + 255) / 256, 256>>>();
    hist_kernel<<<(NE + 255) / 256, 256>>>(edge_dst);
    scan1_kernel<<<NB_SCAN, 1024>>>();
    scan2_kernel<<<1, 64>>>();
    scan3_kernel<<<NB_SCAN, 1024>>>();
    scatter_kernel<<<(NE + 255) / 256, 256>>>(edge_src, edge_dst);

    // Layer 1
    {
        dim3 grid(256 / 64, (NN + 63) / 64);
        gemm_bias_kernel<<<grid, 256>>>(x, Wl1, bl1, fs1, NN, IND, H4 * D1);
        gemm_bias_kernel<<<grid, 256>>>(x, Wr1, br1, fd1, NN, IND, H4 * D1);
    }
    gat_node_kernel<D1><<<(NN * 32 + 255) / 256, 256>>>(fs1, fd1, attn1, h1);

    // Layer 2
    {
        dim3 grid(512 / 64, (NN + 63) / 64);
        gemm_bias_kernel<<<grid, 256>>>(h1, Wl2, bl2, fs2, NN, D1, H4 * D2);
        gemm_bias_kernel<<<grid, 256>>>(h1, Wr2, br2, fd2, NN, D1, H4 * D2);
    }
    gat_node_kernel<D2><<<(NN * 32 + 255) / 256, 256>>>(fs2, fd2, attn2, h2);

    // Global attention pooling
    pool_kernel<<<NG, 128>>>(h2, gate_w, gate_b, out);
}

// round 8
// speedup vs baseline: 1.5069x; 1.5069x over previous
#include <cuda_runtime.h>
#include <math.h>
#include <stdint.h>

#define NN   50000
#define NE   500000
#define NG   50
#define NPG  1000
#define IND  128
#define H4   4
#define D1   64
#define D2   128
#define NB_SCAN ((NN + 1023) / 1024)   // 49

// ---------------- device scratch (no runtime allocation allowed) ----------------
__device__ float g_fs1[NN * H4 * D1];
__device__ float g_fd1[NN * H4 * D1];
__device__ float g_h1 [NN * D1];
__device__ float g_fs2[NN * H4 * D2];
__device__ float g_fd2[NN * H4 * D2];
__device__ float g_h2 [NN * D2];
__device__ int   g_cnt [NN];
__device__ int   g_ptr [NN + 1];
__device__ int   g_cur [NN];
__device__ int   g_csrc[NE];
__device__ int   g_bsum[64];

// ---------------- CSR build ----------------
__global__ void zero_cnt_kernel() {
    int i = blockIdx.x * blockDim.x + threadIdx.x;
    if (i < NN) g_cnt[i] = 0;
}

__global__ void hist_kernel(const int* __restrict__ dst) {
    int e = blockIdx.x * blockDim.x + threadIdx.x;
    if (e < NE) atomicAdd(&g_cnt[dst[e]], 1);
}

__global__ void scan1_kernel() {
    __shared__ int sh[1024];
    int i = blockIdx.x * 1024 + threadIdx.x;
    int v = (i < NN) ? g_cnt[i] : 0;
    sh[threadIdx.x] = v;
    __syncthreads();
    #pragma unroll
    for (int off = 1; off < 1024; off <<= 1) {
        int t = (threadIdx.x >= off) ? sh[threadIdx.x - off] : 0;
        __syncthreads();
        sh[threadIdx.x] += t;
        __syncthreads();
    }
    int incl = sh[threadIdx.x];
    if (i < NN) g_ptr[i] = incl - v;         // block-local exclusive
    if (threadIdx.x == 1023) g_bsum[blockIdx.x] = incl;
}

__global__ void scan2_kernel() {
    __shared__ int sh[64];
    int tid = threadIdx.x;
    int v = (tid < NB_SCAN) ? g_bsum[tid] : 0;
    sh[tid] = v;
    __syncthreads();
    #pragma unroll
    for (int off = 1; off < 64; off <<= 1) {
        int t = (tid >= off) ? sh[tid - off] : 0;
        __syncthreads();
        sh[tid] += t;
        __syncthreads();
    }
    if (tid < NB_SCAN) g_bsum[tid] = sh[tid] - v;  // exclusive across blocks
}

__global__ void scan3_kernel() {
    int i = blockIdx.x * 1024 + threadIdx.x;
    if (i < NN) {
        int p = g_ptr[i] + g_bsum[blockIdx.x];
        g_ptr[i] = p;
        g_cur[i] = p;
    }
    if (i == 0) g_ptr[NN] = NE;
}

__global__ void scatter_kernel(const int* __restrict__ src, const int* __restrict__ dst) {
    int e = blockIdx.x * blockDim.x + threadIdx.x;
    if (e < NE) {
        int d = dst[e];
        int pos = atomicAdd(&g_cur[d], 1);
        g_csrc[pos] = src[e];
    }
}

// ---------------- TF32 tensor-core GEMM ----------------
// C[n,m] = A[n,:] @ W[:,m] + bias[m].  BM=128, BN=64, whole K resident in smem.
// blockIdx.z selects (W0,b0,C0) vs (W1,b1,C1) so both projections of a layer
// share one kernel (A tile is re-read from L2, compute-bound anyway).
// Smem bank analysis: As stride K+4 floats -> bank(row,k)=(4*row+k)%32, all 32
// lanes distinct. Bs stride 72 floats -> bank(k,n)=(8*k+n)%32, distinct.

__device__ __forceinline__ uint32_t f2tf(float f) {
    uint32_t u;
    asm("cvt.rna.tf32.f32 %0, %1;" : "=r"(u) : "f"(f));
    return u;
}

template <int K>
__global__ void __launch_bounds__(256)
gemm_tf32_kernel(const float* __restrict__ A,
                 const float* __restrict__ W0, const float* __restrict__ b0, float* __restrict__ C0,
                 const float* __restrict__ W1, const float* __restrict__ b1, float* __restrict__ C1,
                 int Nr, int M) {
    constexpr int AST = K + 4;   // As row stride (floats)
    constexpr int BST = 72;      // Bs row stride (floats), BN=64
    extern __shared__ uint32_t sm[];
    uint32_t* As = sm;                    // [128][AST]
    uint32_t* Bs = sm + 128 * AST;        // [K][BST]

    const float* W; const float* bias; float* C;
    if (blockIdx.z == 0) { W = W0; bias = b0; C = C0; }
    else                 { W = W1; bias = b1; C = C1; }

    int tid  = threadIdx.x;
    int brow = blockIdx.y * 128;
    int bcol = blockIdx.x * 64;

    // load A tile (128 x K), convert to tf32
    constexpr int KQ = K / 4;
    #pragma unroll
    for (int i = tid; i < 128 * KQ; i += 256) {
        int row = i / KQ, kq = i % KQ;
        float4 v = make_float4(0.f, 0.f, 0.f, 0.f);
        if (brow + row < Nr)
            v = *(const float4*)(A + (size_t)(brow + row) * K + kq * 4);
        uint32_t* d = As + row * AST + kq * 4;
        d[0] = f2tf(v.x); d[1] = f2tf(v.y); d[2] = f2tf(v.z); d[3] = f2tf(v.w);
    }
    // load B tile (K x 64), convert to tf32
    #pragma unroll
    for (int i = tid; i < K * 16; i += 256) {
        int k = i / 16, nq = i % 16;
        float4 v = *(const float4*)(W + (size_t)k * M + bcol + nq * 4);
        uint32_t* d = Bs + k * BST + nq * 4;
        d[0] = f2tf(v.x); d[1] = f2tf(v.y); d[2] = f2tf(v.z); d[3] = f2tf(v.w);
    }
    __syncthreads();

    int lane = tid & 31, wid = tid >> 5;
    int wm = (wid & 3) * 32;      // warp row offset (4 warps x 32 rows)
    int wn = (wid >> 2) * 32;     // warp col offset (2 warps x 32 cols)
    int g  = lane >> 2;           // groupID
    int tg = lane & 3;            // threadID_in_group

    float acc[2][4][4];
    #pragma unroll
    for (int mt = 0; mt < 2; mt++)
        #pragma unroll
        for (int nt = 0; nt < 4; nt++)
            #pragma unroll
            for (int q = 0; q < 4; q++) acc[mt][nt][q] = 0.f;

    #pragma unroll
    for (int ks = 0; ks < K / 8; ks++) {
        uint32_t a[2][4], b[4][2];
        #pragma unroll
        for (int mt = 0; mt < 2; mt++) {
            const uint32_t* p = As + (wm + mt * 16 + g) * AST + ks * 8 + tg;
            a[mt][0] = p[0];
            a[mt][1] = p[8 * AST];
            a[mt][2] = p[4];
            a[mt][3] = p[8 * AST + 4];
        }
        #pragma unroll
        for (int nt = 0; nt < 4; nt++) {
            const uint32_t* p = Bs + (ks * 8 + tg) * BST + wn + nt * 8 + g;
            b[nt][0] = p[0];
            b[nt][1] = p[4 * BST];
        }
        #pragma unroll
        for (int mt = 0; mt < 2; mt++)
            #pragma unroll
            for (int nt = 0; nt < 4; nt++)
                asm volatile(
                    "mma.sync.aligned.m16n8k8.row.col.f32.tf32.tf32.f32 "
                    "{%0,%1,%2,%3},{%4,%5,%6,%7},{%8,%9},{%0,%1,%2,%3};"
                    : "+f"(acc[mt][nt][0]), "+f"(acc[mt][nt][1]),
                      "+f"(acc[mt][nt][2]), "+f"(acc[mt][nt][3])
                    : "r"(a[mt][0]), "r"(a[mt][1]), "r"(a[mt][2]), "r"(a[mt][3]),
                      "r"(b[nt][0]), "r"(b[nt][1]));
    }

    // epilogue: c0:(g,2tg) c1:(g,2tg+1) c2:(g+8,2tg) c3:(g+8,2tg+1)
    #pragma unroll
    for (int mt = 0; mt < 2; mt++) {
        #pragma unroll
        for (int nt = 0; nt < 4; nt++) {
            int c  = bcol + wn + nt * 8 + 2 * tg;
            float bc0 = bias[c], bc1 = bias[c + 1];
            int r0 = brow + wm + mt * 16 + g;
            if (r0 < Nr) {
                float2 v = make_float2(acc[mt][nt][0] + bc0, acc[mt][nt][1] + bc1);
                *(float2*)(C + (size_t)r0 * M + c) = v;
            }
            int r1 = r0 + 8;
            if (r1 < Nr) {
                float2 v = make_float2(acc[mt][nt][2] + bc0, acc[mt][nt][3] + bc1);
                *(float2*)(C + (size_t)r1 * M + c) = v;
            }
        }
    }
}

// ---------------- GAT layer: warp per destination node, online softmax ----------------
template <int D>
__global__ void gat_node_kernel(const float* __restrict__ fs, const float* __restrict__ fd,
                                const float* __restrict__ attn,   // [4, D]
                                float* __restrict__ out) {        // [NN, D]
    constexpr int WI = D / 32;
    int warp = (blockIdx.x * blockDim.x + threadIdx.x) >> 5;
    if (warp >= NN) return;
    int lane = threadIdx.x & 31;
    int node = warp;
    int beg = g_ptr[node];
    int end = g_ptr[node + 1];

    float fdv[H4][WI], av[H4][WI];
    const float* fdrow = fd + (size_t)node * H4 * D;
    #pragma unroll
    for (int h = 0; h < H4; h++)
        #pragma unroll
        for (int i = 0; i < WI; i++) {
            fdv[h][i] = fdrow[h * D + lane + 32 * i];
            av[h][i]  = attn[h * D + lane + 32 * i];
        }

    float m[H4], s[H4], acc[H4][WI];
    #pragma unroll
    for (int h = 0; h < H4; h++) {
        m[h] = -3.0e38f; s[h] = 0.0f;
        #pragma unroll
        for (int i = 0; i < WI; i++) acc[h][i] = 0.0f;
    }

    for (int e = beg; e < end; e++) {
        int srcn = g_csrc[e];
        const float* fr = fs + (size_t)srcn * H4 * D;
        float frv[H4][WI];
        #pragma unroll
        for (int h = 0; h < H4; h++) {
            #pragma unroll
            for (int i = 0; i < WI; i++) frv[h][i] = fr[h * D + lane + 32 * i];
        }
        #pragma unroll
        for (int h = 0; h < H4; h++) {
            float p = 0.0f;
            #pragma unroll
            for (int i = 0; i < WI; i++) {
                float v = frv[h][i] + fdv[h][i];
                v = (v > 0.0f) ? v : 0.2f * v;   // leaky_relu slope 0.2
                p += av[h][i] * v;
            }
            #pragma unroll
            for (int off = 16; off > 0; off >>= 1)
                p += __shfl_xor_sync(0xffffffffu, p, off);
            float nm = fmaxf(m[h], p);
            float cs = __expf(m[h] - nm);
            float w  = __expf(p - nm);
            s[h] = s[h] * cs + w;
            #pragma unroll
            for (int i = 0; i < WI; i++)
                acc[h][i] = acc[h][i] * cs + w * frv[h][i];
            m[h] = nm;
        }
    }

    float* orow = out + (size_t)node * D;
    if (end > beg) {
        #pragma unroll
        for (int i = 0; i < WI; i++) {
            float o = -3.0e38f;
            #pragma unroll
            for (int h = 0; h < H4; h++) o = fmaxf(o, acc[h][i] / s[h]);
            orow[lane + 32 * i] = o;
        }
    } else {
        #pragma unroll
        for (int i = 0; i < WI; i++) orow[lane + 32 * i] = 0.0f;
    }
}

// ---------------- Global attention pooling: one block per graph ----------------
__global__ void pool_kernel(const float* __restrict__ h, const float* __restrict__ gw,
                            const float* __restrict__ gb, float* __restrict__ out) {
    __shared__ float gates[NPG];
    __shared__ float red[128];
    int g = blockIdx.x;
    int tid = threadIdx.x;
    int base = g * NPG;

    for (int n = tid; n < NPG; n += 128) {
        const float* row = h + (size_t)(base + n) * D2;
        float sdot = 0.0f;
        #pragma unroll 4
        for (int d = 0; d < D2; d++) sdot += row[d] * gw[d];
        gates[n] = sdot + gb[0];
    }
    __syncthreads();

    float mx = -3.0e38f;
    for (int n = tid; n < NPG; n += 128) mx = fmaxf(mx, gates[n]);
    red[tid] = mx;
    __syncthreads();
    for (int o = 64; o > 0; o >>= 1) {
        if (tid < o) red[tid] = fmaxf(red[tid], red[tid + o]);
        __syncthreads();
    }
    mx = red[0];
    __syncthreads();

    float ssum = 0.0f;
    for (int n = tid; n < NPG; n += 128) ssum += __expf(gates[n] - mx);
    red[tid] = ssum;
    __syncthreads();
    for (int o = 64; o > 0; o >>= 1) {
        if (tid < o) red[tid] += red[tid + o];
        __syncthreads();
    }
    float S = red[0];

    float acc = 0.0f;
    for (int n = 0; n < NPG; n++) {
        float w = __expf(gates[n] - mx);
        acc += w * h[(size_t)(base + n) * D2 + tid];
    }
    out[g * D2 + tid] = acc / S;
}

// ---------------- launch ----------------
extern "C" void kernel_launch(void* const* d_in, const int* in_sizes, int n_in,
                              void* d_out, int out_size) {
    const float* x        = (const float*)d_in[0];
    const int*   edge_src = (const int*)  d_in[1];
    const int*   edge_dst = (const int*)  d_in[2];
    // d_in[3] = node_graph (graphs are contiguous blocks of 1000 nodes)
    const float* Wl1   = (const float*)d_in[4];
    const float* bl1   = (const float*)d_in[5];
    const float* Wr1   = (const float*)d_in[6];
    const float* br1   = (const float*)d_in[7];
    const float* attn1 = (const float*)d_in[8];
    const float* Wl2   = (const float*)d_in[9];
    const float* bl2   = (const float*)d_in[10];
    const float* Wr2   = (const float*)d_in[11];
    const float* br2   = (const float*)d_in[12];
    const float* attn2 = (const float*)d_in[13];
    const float* gate_w = (const float*)d_in[14];
    const float* gate_b = (const float*)d_in[15];
    float* out = (float*)d_out;

    float *fs1, *fd1, *h1, *fs2, *fd2, *h2;
    cudaGetSymbolAddress((void**)&fs1, g_fs1);
    cudaGetSymbolAddress((void**)&fd1, g_fd1);
    cudaGetSymbolAddress((void**)&h1,  g_h1);
    cudaGetSymbolAddress((void**)&fs2, g_fs2);
    cudaGetSymbolAddress((void**)&fd2, g_fd2);
    cudaGetSymbolAddress((void**)&h2,  g_h2);

    // dynamic smem opt-in (immediate API call, not stream work; capture-safe)
    const int smem1 = (128 * (IND + 4) + IND * 72) * 4;   // 104448 B (K=128)
    const int smem2 = (128 * (D1 + 4)  + D1 * 72) * 4;    //  53248 B (K=64)
    cudaFuncSetAttribute(gemm_tf32_kernel<IND>, cudaFuncAttributeMaxDynamicSharedMemorySize, smem1);
    cudaFuncSetAttribute(gemm_tf32_kernel<D1>,  cudaFuncAttributeMaxDynamicSharedMemorySize, smem2);

    // CSR by destination
    zero_cnt_kernel<<<(NN + 255) / 256, 256>>>();
    hist_kernel<<<(NE + 255) / 256, 256>>>(edge_dst);
    scan1_kernel<<<NB_SCAN, 1024>>>();
    scan2_kernel<<<1, 64>>>();
    scan3_kernel<<<NB_SCAN, 1024>>>();
    scatter_kernel<<<(NE + 255) / 256, 256>>>(edge_src, edge_dst);

    // Layer 1: fs1 = x@Wl1+bl1, fd1 = x@Wr1+br1  (fused via grid.z)
    {
        dim3 grid(256 / 64, (NN + 127) / 128, 2);
        gemm_tf32_kernel<IND><<<grid, 256, smem1>>>(x, Wl1, bl1, fs1, Wr1, br1, fd1, NN, 256);
    }
    gat_node_kernel<D1><<<(NN * 32 + 255) / 256, 256>>>(fs1, fd1, attn1, h1);

    // Layer 2
    {
        dim3 grid(512 / 64, (NN + 127) / 128, 2);
        gemm_tf32_kernel<D1><<<grid, 256, smem2>>>(h1, Wl2, bl2, fs2, Wr2, br2, fd2, NN, 512);
    }
    gat_node_kernel<D2><<<(NN * 32 + 255) / 256, 256>>>(fs2, fd2, attn2, h2);

    // Global attention pooling
    pool_kernel<<<NG, 128>>>(h2, gate_w, gate_b, out);
}